// round 1
// baseline (speedup 1.0000x reference)
#include <cuda_runtime.h>
#include <cuda_bf16.h>
#include <math.h>

// Fused: Conv3d(3->24,k=3,VALID) -> min over D -> softmax over C
// x: [16,3,32,128,128]  w: [24,3,3,3,3]  b: [24]  out: [16,24,1,126,126]
//
// Block: (n, 4 output rows, all 126 cols). 256 threads = 4 channel-groups x 64.
// Thread: 6 channels x 4 f32x2 pixel-pairs (8 px). FFMA2 (fma.rn.f32x2) main loop.
// Rolling 4-slice smem ring over depth, 1 barrier per depth step.

typedef unsigned long long u64;

#define TH 4                 // output rows per block
#define SLICE_FLOATS (3*(TH+2)*128)   // 2304
#define W2_FLOATS (81*24*2)           // 3888 duplicated weight pairs
#define SMEM_FLOATS (W2_FLOATS + 4*SLICE_FLOATS + 16)  // 13120
#define SMEM_BYTES (SMEM_FLOATS*4)    // 52480

__device__ __forceinline__ u64 ffma2(u64 a, u64 b, u64 c) {
    u64 d;
    asm("fma.rn.f32x2 %0, %1, %2, %3;" : "=l"(d) : "l"(a), "l"(b), "l"(c));
    return d;
}
__device__ __forceinline__ float f2lo(u64 a) { return __uint_as_float((unsigned)(a & 0xffffffffull)); }
__device__ __forceinline__ float f2hi(u64 a) { return __uint_as_float((unsigned)(a >> 32)); }

__global__ void __launch_bounds__(256, 2)
fused_conv_min_softmax(const float* __restrict__ x,
                       const float* __restrict__ wgt,
                       const float* __restrict__ bias,
                       float* __restrict__ out)
{
    extern __shared__ float smem[];
    float* s_w2 = smem;              // [ (kd,ci,kh,kw) ][co][2]  duplicated pairs
    float* s_sl = smem + W2_FLOATS;  // 4 rolling slices of [ci][TH+2][128]
    // softmax buffer aliases smem[0 .. 24*504) after the depth loop

    const int tid   = threadIdx.x;
    const int n     = blockIdx.y;
    const int h0    = blockIdx.x * TH;

    const int g     = tid >> 6;        // channel group, co = 6g..6g+5
    const int L     = tid & 63;
    const int r_loc = L >> 4;          // local output row 0..3
    const int j     = L & 15;          // 16 threads cover 126 cols
    const int w0    = j << 3;          // first output col (8 px per thread)

    // ---- duplicate weights into smem: [kd][ci][kh][kw][co][2] ----
    for (int idx = tid; idx < 1944; idx += 256) {
        int co = idx / 81, t = idx % 81;
        int ci = t / 27;   t %= 27;
        int kd = t / 9;
        int kh = (t % 9) / 3;
        int kw = t % 3;
        float v = wgt[idx];
        int dst = ((((kd*3 + ci)*3 + kh)*3 + kw) * 48) + co*2;
        s_w2[dst]   = v;
        s_w2[dst+1] = v;
    }

    // ---- slice loader: x[n][ci][z][h0..h0+5][0..127] -> buf[ci][r][128] ----
    auto load_slice = [&](int z, float* buf) {
        for (int q = tid; q < 576; q += 256) {          // 576 float4 per slice
            int ci = q / 192;
            int rr = (q % 192) >> 5;
            int c4 = q & 31;
            int h  = h0 + rr; if (h > 127) h = 127;     // clamp edge tile
            const float4 v = *reinterpret_cast<const float4*>(
                x + ((((size_t)(n*3 + ci)) * 32 + z) << 14) + (h << 7) + (c4 << 2));
            *reinterpret_cast<float4*>(buf + (ci*6 + rr)*128 + (c4 << 2)) = v;
        }
    };

    load_slice(0, s_sl + 0*SLICE_FLOATS);
    load_slice(1, s_sl + 1*SLICE_FLOATS);

    const float INF = __int_as_float(0x7f800000);
    float mlo[6][4], mhi[6][4];
    #pragma unroll
    for (int c = 0; c < 6; ++c)
        #pragma unroll
        for (int p = 0; p < 4; ++p) { mlo[c][p] = INF; mhi[c][p] = INF; }

    const float* wg_base = s_w2 + g*12;   // channel-group offset (co*2)

    for (int d = 0; d < 30; ++d) {
        load_slice(d + 2, s_sl + ((d + 2) & 3) * SLICE_FLOATS);
        __syncthreads();   // between barrier(k) and barrier(k+1) only compute(d-?) / this load coexist; ring of 4 keeps them disjoint

        u64 acc[6][4];
        #pragma unroll
        for (int c = 0; c < 6; ++c)
            #pragma unroll
            for (int p = 0; p < 4; ++p) acc[c][p] = 0ull;

        #pragma unroll 1
        for (int kd = 0; kd < 3; ++kd) {
            const float* B   = s_sl + ((d + kd) & 3) * SLICE_FLOATS;
            const float* wkd = wg_base + kd * 1296;
            #pragma unroll
            for (int ci = 0; ci < 3; ++ci) {
                #pragma unroll
                for (int kh = 0; kh < 3; ++kh) {
                    const float* rp = B + (ci*6 + r_loc + kh)*128 + w0;
                    u64 a0 = *reinterpret_cast<const u64*>(rp);
                    u64 a1 = *reinterpret_cast<const u64*>(rp + 2);
                    u64 a2 = *reinterpret_cast<const u64*>(rp + 4);
                    u64 a3 = *reinterpret_cast<const u64*>(rp + 6);
                    u64 a4 = *reinterpret_cast<const u64*>(rp + 8);
                    u64 b0 = (a0 >> 32) | (a1 << 32);   // (x1,x2)
                    u64 b1 = (a1 >> 32) | (a2 << 32);
                    u64 b2 = (a2 >> 32) | (a3 << 32);
                    u64 b3 = (a3 >> 32) | (a4 << 32);
                    const float* wr = wkd + ci*432 + kh*144;
                    #pragma unroll
                    for (int c = 0; c < 6; ++c) {
                        u64 wp0 = *reinterpret_cast<const u64*>(wr + c*2);        // kw=0 (dup pair)
                        u64 wp1 = *reinterpret_cast<const u64*>(wr + 48 + c*2);   // kw=1
                        u64 wp2 = *reinterpret_cast<const u64*>(wr + 96 + c*2);   // kw=2
                        acc[c][0] = ffma2(a0, wp0, acc[c][0]);
                        acc[c][1] = ffma2(a1, wp0, acc[c][1]);
                        acc[c][2] = ffma2(a2, wp0, acc[c][2]);
                        acc[c][3] = ffma2(a3, wp0, acc[c][3]);
                        acc[c][0] = ffma2(b0, wp1, acc[c][0]);
                        acc[c][1] = ffma2(b1, wp1, acc[c][1]);
                        acc[c][2] = ffma2(b2, wp1, acc[c][2]);
                        acc[c][3] = ffma2(b3, wp1, acc[c][3]);
                        acc[c][0] = ffma2(a1, wp2, acc[c][0]);
                        acc[c][1] = ffma2(a2, wp2, acc[c][1]);
                        acc[c][2] = ffma2(a3, wp2, acc[c][2]);
                        acc[c][3] = ffma2(a4, wp2, acc[c][3]);
                    }
                }
            }
        }

        #pragma unroll
        for (int c = 0; c < 6; ++c)
            #pragma unroll
            for (int p = 0; p < 4; ++p) {
                mlo[c][p] = fminf(mlo[c][p], f2lo(acc[c][p]));
                mhi[c][p] = fminf(mhi[c][p], f2hi(acc[c][p]));
            }
    }

    // ---- stash min+bias into smem transpose buffer sf[24][504] ----
    __syncthreads();                  // all weight/slice reads done; safe to alias
    float* sf = smem;
    if (h0 + r_loc < 126) {
        #pragma unroll
        for (int c = 0; c < 6; ++c) {
            int co = g*6 + c;
            float bv = __ldg(&bias[co]);
            float* row = sf + co*504 + r_loc*126;
            #pragma unroll
            for (int p = 0; p < 4; ++p) {
                int wa = w0 + 2*p;
                if (wa     < 126) row[wa]     = mlo[c][p] + bv;
                if (wa + 1 < 126) row[wa + 1] = mhi[c][p] + bv;
            }
        }
    }
    __syncthreads();

    // ---- softmax over 24 channels, write out ----
    int vrows = 126 - h0; if (vrows > TH) vrows = TH;
    for (int px = tid; px < vrows * 126; px += 256) {
        float v[24];
        float m = -INF;
        #pragma unroll
        for (int c = 0; c < 24; ++c) { v[c] = sf[c*504 + px]; m = fmaxf(m, v[c]); }
        float s = 0.f;
        #pragma unroll
        for (int c = 0; c < 24; ++c) { v[c] = expf(v[c] - m); s += v[c]; }
        float inv = 1.0f / s;
        int r = px / 126, ww = px % 126;
        size_t ob = (size_t)n * 24 * 15876 + (size_t)(h0 + r) * 126 + ww;
        #pragma unroll
        for (int c = 0; c < 24; ++c)
            out[ob + (size_t)c * 15876] = v[c] * inv;
    }
}

extern "C" void kernel_launch(void* const* d_in, const int* in_sizes, int n_in,
                              void* d_out, int out_size) {
    const float* x    = (const float*)d_in[0];
    const float* wgt  = (const float*)d_in[1];
    const float* bias = (const float*)d_in[2];
    float* out        = (float*)d_out;

    cudaFuncSetAttribute(fused_conv_min_softmax,
                         cudaFuncAttributeMaxDynamicSharedMemorySize, SMEM_BYTES);

    dim3 grid(32, 16);   // 32 h-tiles (ceil(126/4)), 16 batches
    fused_conv_min_softmax<<<grid, 256, SMEM_BYTES>>>(x, wgt, bias, out);
}

// round 2
// speedup vs baseline: 1.0416x; 1.0416x over previous
#include <cuda_runtime.h>
#include <cuda_bf16.h>
#include <math.h>

// Kernel 1: Conv3d(3->24,k=3,VALID) + min over depth + bias -> d_out [16,24,126,126]
//   Block: 192 thr = 2 ch-groups(6ch) x (3 rows x 32 col-threads, 4 px each).
//   Grid (42 htiles, 16 n, 2 ch-halves). Ring-4 smem depth pipeline, FFMA2 core.
// Kernel 2: in-place softmax over the 24-channel dim of d_out.

typedef unsigned long long u64;

#define TH 3
#define ROWS_IN (TH + 2)                       // 5
#define SLICE_FLOATS (3 * ROWS_IN * 128)       // 1920
#define W_FLOATS (81 * 12 * 2)                 // 1944
#define SMEM_FLOATS (W_FLOATS + 4 * SLICE_FLOATS + 16)  // 9640
#define SMEM_BYTES (SMEM_FLOATS * 4)           // 38560

__device__ __forceinline__ u64 ffma2(u64 a, u64 b, u64 c) {
    u64 d;
    asm("fma.rn.f32x2 %0, %1, %2, %3;" : "=l"(d) : "l"(a), "l"(b), "l"(c));
    return d;
}
__device__ __forceinline__ float f2lo(u64 a) { return __uint_as_float((unsigned)(a & 0xffffffffull)); }
__device__ __forceinline__ float f2hi(u64 a) { return __uint_as_float((unsigned)(a >> 32)); }

__global__ void __launch_bounds__(192, 3)
conv_min_bias(const float* __restrict__ x,
              const float* __restrict__ wgt,
              const float* __restrict__ bias,
              float* __restrict__ out)
{
    extern __shared__ float smem[];
    float* s_w  = smem;                 // [tap=81][cc=12][2] duplicated weight pairs
    float* s_sl = smem + W_FLOATS;      // ring of 4 slices [ci][5][128]

    const int tid = threadIdx.x;
    const int h0  = blockIdx.x * TH;
    const int n   = blockIdx.y;
    const int ch0 = blockIdx.z * 12;

    const int g2    = tid / 96;         // 0..1 -> channels ch0+g2*6 .. +5
    const int L     = tid % 96;
    const int r_loc = L >> 5;           // 0..2
    const int j     = L & 31;
    const int w0    = j << 2;           // first col (4 px per thread)

    // ---- weights -> smem, duplicated pairs: s_w[tap*24 + cc*2 {,+1}] ----
    for (int idx = tid; idx < 972; idx += 192) {
        int cc = idx / 81, t = idx % 81;
        int ci = t / 27;  t %= 27;
        int kd = t / 9;
        int kh = (t % 9) / 3;
        int kw = t % 3;
        float v = wgt[(ch0 + cc) * 81 + (idx % 81)];
        int dst = (((kd * 3 + ci) * 3 + kh) * 3 + kw) * 24 + cc * 2;
        s_w[dst]     = v;
        s_w[dst + 1] = v;
    }

    // ---- slice loader: x[n][ci][z][h0..h0+4][:] -> buf[ci][rr][128] ----
    auto load_slice = [&](int z, float* buf) {
        for (int q = tid; q < 480; q += 192) {            // 480 float4 per slice
            int ci = q / 160;
            int rr = (q % 160) >> 5;
            int c4 = q & 31;
            const float4 v = *reinterpret_cast<const float4*>(
                x + ((((size_t)(n * 3 + ci)) * 32 + z) << 14) + ((h0 + rr) << 7) + (c4 << 2));
            *reinterpret_cast<float4*>(buf + (ci * ROWS_IN + rr) * 128 + (c4 << 2)) = v;
        }
    };

    load_slice(0, s_sl);
    load_slice(1, s_sl + SLICE_FLOATS);

    const float INF = __int_as_float(0x7f800000);
    float mlo[6][2], mhi[6][2];
    #pragma unroll
    for (int c = 0; c < 6; ++c) {
        mlo[c][0] = INF; mlo[c][1] = INF;
        mhi[c][0] = INF; mhi[c][1] = INF;
    }

    const float* wg = s_w + g2 * 12;

    for (int d = 0; d < 30; ++d) {
        load_slice(d + 2, s_sl + ((d + 2) & 3) * SLICE_FLOATS);
        __syncthreads();   // ring of 4 keeps prefetch(d+2) disjoint from compute(d-1..d)

        u64 acc[6][2];
        #pragma unroll
        for (int c = 0; c < 6; ++c) { acc[c][0] = 0ull; acc[c][1] = 0ull; }

        #pragma unroll 1
        for (int kd = 0; kd < 3; ++kd) {
            const float* B = s_sl + ((d + kd) & 3) * SLICE_FLOATS;
            #pragma unroll
            for (int ci = 0; ci < 3; ++ci) {
                #pragma unroll
                for (int kh = 0; kh < 3; ++kh) {
                    const float* rp = B + (ci * ROWS_IN + r_loc + kh) * 128 + w0;
                    const ulonglong2 A = *reinterpret_cast<const ulonglong2*>(rp);
                    const u64 a0 = A.x, a1 = A.y;
                    const u64 a2 = *reinterpret_cast<const u64*>(rp + 4);
                    const u64 b0 = (a0 >> 32) | (a1 << 32);
                    const u64 b1 = (a1 >> 32) | (a2 << 32);
                    const float* wb = wg + ((kd * 3 + ci) * 3 + kh) * 72;  // tap0*24
                    #pragma unroll
                    for (int cp = 0; cp < 3; ++cp) {
                        const ulonglong2 W0 = *reinterpret_cast<const ulonglong2*>(wb + cp * 4);
                        const ulonglong2 W1 = *reinterpret_cast<const ulonglong2*>(wb + 24 + cp * 4);
                        const ulonglong2 W2 = *reinterpret_cast<const ulonglong2*>(wb + 48 + cp * 4);
                        const int c0 = 2 * cp, c1 = 2 * cp + 1;
                        acc[c0][0] = ffma2(a0, W0.x, acc[c0][0]);
                        acc[c0][1] = ffma2(a1, W0.x, acc[c0][1]);
                        acc[c1][0] = ffma2(a0, W0.y, acc[c1][0]);
                        acc[c1][1] = ffma2(a1, W0.y, acc[c1][1]);
                        acc[c0][0] = ffma2(b0, W1.x, acc[c0][0]);
                        acc[c0][1] = ffma2(b1, W1.x, acc[c0][1]);
                        acc[c1][0] = ffma2(b0, W1.y, acc[c1][0]);
                        acc[c1][1] = ffma2(b1, W1.y, acc[c1][1]);
                        acc[c0][0] = ffma2(a1, W2.x, acc[c0][0]);
                        acc[c0][1] = ffma2(a2, W2.x, acc[c0][1]);
                        acc[c1][0] = ffma2(a1, W2.y, acc[c1][0]);
                        acc[c1][1] = ffma2(a2, W2.y, acc[c1][1]);
                    }
                }
            }
        }

        #pragma unroll
        for (int c = 0; c < 6; ++c) {
            mlo[c][0] = fminf(mlo[c][0], f2lo(acc[c][0]));
            mhi[c][0] = fminf(mhi[c][0], f2hi(acc[c][0]));
            mlo[c][1] = fminf(mlo[c][1], f2lo(acc[c][1]));
            mhi[c][1] = fminf(mhi[c][1], f2hi(acc[c][1]));
        }
    }

    // ---- epilogue: min + bias -> gmem (softmax is a second kernel) ----
    const int h = h0 + r_loc;           // always < 126 (42*3 = 126 exact)
    #pragma unroll
    for (int c = 0; c < 6; ++c) {
        const int co = ch0 + g2 * 6 + c;
        const float bv = __ldg(&bias[co]);
        float* op = out + ((size_t)n * 24 + co) * 15876 + h * 126 + w0;
        *reinterpret_cast<float2*>(op) = make_float2(mlo[c][0] + bv, mhi[c][0] + bv);
        if (w0 + 2 < 126)
            *reinterpret_cast<float2*>(op + 2) = make_float2(mlo[c][1] + bv, mhi[c][1] + bv);
    }
}

__global__ void __launch_bounds__(256)
softmax24(float* __restrict__ out)
{
    const int px = blockIdx.x * 256 + threadIdx.x;
    if (px >= 15876) return;
    float* p = out + (size_t)blockIdx.y * 24 * 15876 + px;

    float v[24];
    float m = -__int_as_float(0x7f800000);
    #pragma unroll
    for (int c = 0; c < 24; ++c) { v[c] = p[(size_t)c * 15876]; m = fmaxf(m, v[c]); }
    float s = 0.f;
    #pragma unroll
    for (int c = 0; c < 24; ++c) { v[c] = __expf(v[c] - m); s += v[c]; }
    const float inv = 1.0f / s;
    #pragma unroll
    for (int c = 0; c < 24; ++c) p[(size_t)c * 15876] = v[c] * inv;
}

extern "C" void kernel_launch(void* const* d_in, const int* in_sizes, int n_in,
                              void* d_out, int out_size) {
    const float* x    = (const float*)d_in[0];
    const float* wgt  = (const float*)d_in[1];
    const float* bias = (const float*)d_in[2];
    float* out        = (float*)d_out;

    cudaFuncSetAttribute(conv_min_bias,
                         cudaFuncAttributeMaxDynamicSharedMemorySize, SMEM_BYTES);

    dim3 g1(42, 16, 2);                 // 1344 blocks = 3.03 waves at occ 3
    conv_min_bias<<<g1, 192, SMEM_BYTES>>>(x, wgt, bias, out);

    dim3 g2(63, 16);
    softmax24<<<g2, 256>>>(out);
}

// round 4
// speedup vs baseline: 1.1249x; 1.0800x over previous
#include <cuda_runtime.h>
#include <cuda_bf16.h>
#include <math.h>

// Kernel 1: Conv3d(3->24,k=3,VALID) + min over depth + bias -> d_out [16,24,126,126]
//   Depth-chunked (D=2): each weight LDS amortized over 2 depths x 4 px x 2 ch.
//   cp.async slice prefetch into a ring of 6, one barrier per chunk (15 total).
// Kernel 2: in-place softmax over channels.

typedef unsigned long long u64;

#define TH 4
#define ROWS_IN (TH + 2)                          // 6
#define SLICE_FLOATS (3 * ROWS_IN * 128)          // 2304
#define RING 6
#define W_FLOATS (81 * 12 * 2)                    // 1944
#define SMEM_FLOATS (W_FLOATS + RING * SLICE_FLOATS + 8)   // 15776
#define SMEM_BYTES (SMEM_FLOATS * 4)              // 63104

__device__ __forceinline__ u64 ffma2(u64 a, u64 b, u64 c) {
    u64 d;
    asm("fma.rn.f32x2 %0, %1, %2, %3;" : "=l"(d) : "l"(a), "l"(b), "l"(c));
    return d;
}
__device__ __forceinline__ float f2lo(u64 a) { return __uint_as_float((unsigned)(a & 0xffffffffull)); }
__device__ __forceinline__ float f2hi(u64 a) { return __uint_as_float((unsigned)(a >> 32)); }

__device__ __forceinline__ void cpasync16(const float* s_dst, const float* g_src) {
    unsigned saddr = (unsigned)__cvta_generic_to_shared(s_dst);
    asm volatile("cp.async.cg.shared.global [%0], [%1], 16;" :: "r"(saddr), "l"(g_src));
}

__global__ void __launch_bounds__(256, 2)
conv_min_bias(const float* __restrict__ x,
              const float* __restrict__ wgt,
              const float* __restrict__ bias,
              float* __restrict__ out)
{
    extern __shared__ float smem[];
    float* s_w  = smem;                // [kd][ci][kh][kw][cc=12][2] duplicated pairs
    float* s_sl = smem + W_FLOATS;     // ring of 6 slices [ci][6][128]

    const int tid = threadIdx.x;
    const int h0  = blockIdx.x * TH;
    const int n   = blockIdx.y;
    const int ch0 = blockIdx.z * 12;

    const int g2    = tid >> 7;        // 0..1 -> channels ch0+g2*6 .. +5
    const int L     = tid & 127;
    const int r_loc = L >> 5;          // 0..3
    const int j     = L & 31;
    const int w0    = j << 2;          // 4 px per thread

    // ---- weights -> smem duplicated pairs ----
    for (int idx = tid; idx < 972; idx += 256) {
        int cc = idx / 81, t = idx % 81;
        int ci = t / 27;  t %= 27;
        int kd = t / 9;
        int kh = (t % 9) / 3;
        int kw = t % 3;
        float v = wgt[(ch0 + cc) * 81 + (idx % 81)];
        int dst = (((kd * 3 + ci) * 3 + kh) * 3 + kw) * 24 + cc * 2;
        s_w[dst]     = v;
        s_w[dst + 1] = v;
    }

    // ---- async slice loader: x[n][ci][z][h0..h0+5][:] -> slot ----
    auto prefetch_slice = [&](int z, int slot) {
        float* buf = s_sl + slot * SLICE_FLOATS;
        for (int q = tid; q < 576; q += 256) {       // 576 float4
            int ci = q / 192;
            int rr = (q % 192) >> 5;
            int c4 = q & 31;
            int h  = h0 + rr; if (h > 127) h = 127;
            cpasync16(buf + (ci * ROWS_IN + rr) * 128 + (c4 << 2),
                      x + ((((size_t)(n * 3 + ci)) * 32 + z) << 14) + (h << 7) + (c4 << 2));
        }
    };

    // prologue: slices z=0..3 into slots 0..3
    prefetch_slice(0, 0);
    prefetch_slice(1, 1);
    prefetch_slice(2, 2);
    prefetch_slice(3, 3);
    asm volatile("cp.async.commit_group;" ::: "memory");
    asm volatile("cp.async.wait_group 0;" ::: "memory");
    __syncthreads();

    const float INF = __int_as_float(0x7f800000);
    float mlo[6][2], mhi[6][2];
    #pragma unroll
    for (int c = 0; c < 6; ++c) {
        mlo[c][0] = INF; mlo[c][1] = INF;
        mhi[c][0] = INF; mhi[c][1] = INF;
    }

    const int   toff = r_loc * 128 + w0;
    const float* wg  = s_w + g2 * 12;

    int s0 = 0;                                  // slot of z = 2*c
    #pragma unroll 1
    for (int c = 0; c < 15; ++c) {
        // prefetch z = 2c+4, 2c+5
        const int zp = 2 * c + 4;
        if (zp < 32) {
            int sl4 = s0 + 4; if (sl4 >= RING) sl4 -= RING;
            int sl5 = s0 + 5; if (sl5 >= RING) sl5 -= RING;
            prefetch_slice(zp,     sl4);
            prefetch_slice(zp + 1, sl5);
        }
        asm volatile("cp.async.commit_group;" ::: "memory");

        // base pointers for input z = 2c + j, j=0..3
        const float* bp[4];
        #pragma unroll
        for (int jj = 0; jj < 4; ++jj) {
            int s = s0 + jj; if (s >= RING) s -= RING;
            bp[jj] = s_sl + s * SLICE_FLOATS + toff;
        }

        u64 acc[2][6][2];
        #pragma unroll
        for (int dz = 0; dz < 2; ++dz)
            #pragma unroll
            for (int cc = 0; cc < 6; ++cc) { acc[dz][cc][0] = 0ull; acc[dz][cc][1] = 0ull; }

        #pragma unroll
        for (int kd = 0; kd < 3; ++kd) {
            const float* B0 = bp[kd];
            const float* B1 = bp[kd + 1];
            const float* wk = wg + kd * 648;          // kd stride: 27 taps * 24
            #pragma unroll 1
            for (int ci = 0; ci < 3; ++ci) {
                const float* x0 = B0 + ci * (ROWS_IN * 128);
                const float* x1 = B1 + ci * (ROWS_IN * 128);
                const float* wc = wk + ci * 216;      // ci stride: 9 taps * 24
                #pragma unroll
                for (int kh = 0; kh < 3; ++kh) {
                    const float* r0 = x0 + kh * 128;
                    const float* r1 = x1 + kh * 128;
                    const ulonglong2 A = *reinterpret_cast<const ulonglong2*>(r0);
                    const u64 a0 = A.x, a1 = A.y;
                    const u64 a2 = *reinterpret_cast<const u64*>(r0 + 4);
                    const u64 b0 = (a0 >> 32) | (a1 << 32);
                    const u64 b1 = (a1 >> 32) | (a2 << 32);
                    const ulonglong2 E = *reinterpret_cast<const ulonglong2*>(r1);
                    const u64 e0 = E.x, e1 = E.y;
                    const u64 e2 = *reinterpret_cast<const u64*>(r1 + 4);
                    const u64 f0 = (e0 >> 32) | (e1 << 32);
                    const u64 f1 = (e1 >> 32) | (e2 << 32);
                    const float* wb = wc + kh * 72;   // kh stride: 3 kw * 24
                    #pragma unroll
                    for (int cp = 0; cp < 3; ++cp) {
                        const ulonglong2 W0 = *reinterpret_cast<const ulonglong2*>(wb + 4 * cp);
                        const ulonglong2 W1 = *reinterpret_cast<const ulonglong2*>(wb + 24 + 4 * cp);
                        const ulonglong2 W2 = *reinterpret_cast<const ulonglong2*>(wb + 48 + 4 * cp);
                        const int c0 = 2 * cp, c1 = 2 * cp + 1;
                        // dz = 0
                        acc[0][c0][0] = ffma2(a0, W0.x, acc[0][c0][0]);
                        acc[0][c0][1] = ffma2(a1, W0.x, acc[0][c0][1]);
                        acc[0][c1][0] = ffma2(a0, W0.y, acc[0][c1][0]);
                        acc[0][c1][1] = ffma2(a1, W0.y, acc[0][c1][1]);
                        acc[0][c0][0] = ffma2(b0, W1.x, acc[0][c0][0]);
                        acc[0][c0][1] = ffma2(b1, W1.x, acc[0][c0][1]);
                        acc[0][c1][0] = ffma2(b0, W1.y, acc[0][c1][0]);
                        acc[0][c1][1] = ffma2(b1, W1.y, acc[0][c1][1]);
                        acc[0][c0][0] = ffma2(a1, W2.x, acc[0][c0][0]);
                        acc[0][c0][1] = ffma2(a2, W2.x, acc[0][c0][1]);
                        acc[0][c1][0] = ffma2(a1, W2.y, acc[0][c1][0]);
                        acc[0][c1][1] = ffma2(a2, W2.y, acc[0][c1][1]);
                        // dz = 1
                        acc[1][c0][0] = ffma2(e0, W0.x, acc[1][c0][0]);
                        acc[1][c0][1] = ffma2(e1, W0.x, acc[1][c0][1]);
                        acc[1][c1][0] = ffma2(e0, W0.y, acc[1][c1][0]);
                        acc[1][c1][1] = ffma2(e1, W0.y, acc[1][c1][1]);
                        acc[1][c0][0] = ffma2(f0, W1.x, acc[1][c0][0]);
                        acc[1][c0][1] = ffma2(f1, W1.x, acc[1][c0][1]);
                        acc[1][c1][0] = ffma2(f0, W1.y, acc[1][c1][0]);
                        acc[1][c1][1] = ffma2(f1, W1.y, acc[1][c1][1]);
                        acc[1][c0][0] = ffma2(e1, W2.x, acc[1][c0][0]);
                        acc[1][c0][1] = ffma2(e2, W2.x, acc[1][c0][1]);
                        acc[1][c1][0] = ffma2(e1, W2.y, acc[1][c1][0]);
                        acc[1][c1][1] = ffma2(e2, W2.y, acc[1][c1][1]);
                    }
                }
            }
        }

        #pragma unroll
        for (int dz = 0; dz < 2; ++dz)
            #pragma unroll
            for (int cc = 0; cc < 6; ++cc)
                #pragma unroll
                for (int p = 0; p < 2; ++p) {
                    mlo[cc][p] = fminf(mlo[cc][p], f2lo(acc[dz][cc][p]));
                    mhi[cc][p] = fminf(mhi[cc][p], f2hi(acc[dz][cc][p]));
                }

        asm volatile("cp.async.wait_group 0;" ::: "memory");
        __syncthreads();

        s0 += 2; if (s0 >= RING) s0 -= RING;
    }

    // ---- epilogue: min + bias -> gmem ----
    const int h = h0 + r_loc;
    if (h < 126) {
        #pragma unroll
        for (int cc = 0; cc < 6; ++cc) {
            const int co = ch0 + g2 * 6 + cc;
            const float bv = __ldg(&bias[co]);
            float* op = out + ((size_t)n * 24 + co) * 15876 + h * 126 + w0;
            *reinterpret_cast<float2*>(op) = make_float2(mlo[cc][0] + bv, mhi[cc][0] + bv);
            if (w0 + 2 < 126)
                *reinterpret_cast<float2*>(op + 2) = make_float2(mlo[cc][1] + bv, mhi[cc][1] + bv);
        }
    }
}

__global__ void __launch_bounds__(256)
softmax24(float* __restrict__ out)
{
    const int px = blockIdx.x * 256 + threadIdx.x;
    if (px >= 15876) return;
    float* p = out + (size_t)blockIdx.y * 24 * 15876 + px;

    float v[24];
    float m = -__int_as_float(0x7f800000);
    #pragma unroll
    for (int c = 0; c < 24; ++c) { v[c] = p[(size_t)c * 15876]; m = fmaxf(m, v[c]); }
    float s = 0.f;
    #pragma unroll
    for (int c = 0; c < 24; ++c) { v[c] = __expf(v[c] - m); s += v[c]; }
    const float inv = 1.0f / s;
    #pragma unroll
    for (int c = 0; c < 24; ++c) p[(size_t)c * 15876] = v[c] * inv;
}

extern "C" void kernel_launch(void* const* d_in, const int* in_sizes, int n_in,
                              void* d_out, int out_size) {
    const float* x    = (const float*)d_in[0];
    const float* wgt  = (const float*)d_in[1];
    const float* bias = (const float*)d_in[2];
    float* out        = (float*)d_out;

    cudaFuncSetAttribute(conv_min_bias,
                         cudaFuncAttributeMaxDynamicSharedMemorySize, SMEM_BYTES);

    dim3 g1(32, 16, 2);                 // ceil(126/4) h-tiles, 16 n, 2 ch-halves
    conv_min_bias<<<g1, 256, SMEM_BYTES>>>(x, wgt, bias, out);

    dim3 g2(63, 16);
    softmax24<<<g2, 256>>>(out);
}

// round 5
// speedup vs baseline: 1.2023x; 1.0688x over previous
#include <cuda_runtime.h>
#include <cuda_bf16.h>
#include <math.h>

// Single fused kernel: Conv3d(3->24,k=3,VALID) + min over depth + bias + channel softmax.
// x: [16,3,32,128,128] -> out: [16,24,1,126,126]
// Block: 256 thr = 4 ch-groups(6ch) x (2 rows x 32 cols, 4px). Grid (63, 16).
// Depth-chunked D=2, ring-6 cp.async slice pipeline, FFMA2 core,
// x-rows cached across the kd loop, softmax epilogue via smem transpose.

typedef unsigned long long u64;

#define TH 2
#define ROWS_IN 4
#define SLICE_FLOATS (3 * ROWS_IN * 128)          // 1536
#define RING 6
#define W_FLOATS (81 * 24 * 2)                    // 3888
#define SF_STRIDE 256
#define SMEM_FLOATS (W_FLOATS + RING * SLICE_FLOATS + 16)  // 13120
#define SMEM_BYTES (SMEM_FLOATS * 4)              // 52480

__device__ __forceinline__ u64 ffma2(u64 a, u64 b, u64 c) {
    u64 d;
    asm("fma.rn.f32x2 %0, %1, %2, %3;" : "=l"(d) : "l"(a), "l"(b), "l"(c));
    return d;
}
__device__ __forceinline__ u64 mkpair(u64 lo_src, u64 hi_src) {
    // (lo_src.hi, hi_src.lo)
    return (lo_src >> 32) | (hi_src << 32);
}
__device__ __forceinline__ float f2lo(u64 a) { return __uint_as_float((unsigned)(a & 0xffffffffull)); }
__device__ __forceinline__ float f2hi(u64 a) { return __uint_as_float((unsigned)(a >> 32)); }

__device__ __forceinline__ void cpasync16(const float* s_dst, const float* g_src) {
    unsigned saddr = (unsigned)__cvta_generic_to_shared(s_dst);
    asm volatile("cp.async.cg.shared.global [%0], [%1], 16;" :: "r"(saddr), "l"(g_src));
}

__global__ void __launch_bounds__(256, 2)
fused_conv_min_softmax(const float* __restrict__ x,
                       const float* __restrict__ wgt,
                       const float* __restrict__ bias,
                       float* __restrict__ out)
{
    extern __shared__ float smem[];
    float* s_w  = smem;                 // [kd][ci][kh][kw][cc=24][2] duplicated pairs
    float* s_sl = smem + W_FLOATS;      // ring of 6 slices [ci][4][128]

    const int tid = threadIdx.x;
    const int h0  = blockIdx.x * TH;    // 0..124
    const int n   = blockIdx.y;

    const int g     = tid >> 6;         // 0..3 -> channels 6g..6g+5
    const int L     = tid & 63;
    const int r_loc = L >> 5;           // 0..1
    const int j     = L & 31;
    const int w0    = j << 2;           // 4 px per thread

    // ---- weights -> smem duplicated pairs ----
    for (int idx = tid; idx < 1944; idx += 256) {
        int cc = idx / 81, t = idx % 81;
        int ci = t / 27;  t %= 27;
        int kd = t / 9;
        int kh = (t % 9) / 3;
        int kw = t % 3;
        float v = wgt[idx];
        int dst = (((kd * 3 + ci) * 3 + kh) * 3 + kw) * 48 + cc * 2;
        s_w[dst]     = v;
        s_w[dst + 1] = v;
    }

    // ---- async slice loader: x[n][ci][z][h0..h0+3][:] -> slot ----
    auto prefetch_slice = [&](int z, int slot) {
        float* buf = s_sl + slot * SLICE_FLOATS;
        for (int q = tid; q < 384; q += 256) {      // 384 float4 per slice
            int ci = q >> 7;
            int rr = (q & 127) >> 5;
            int c4 = q & 31;
            cpasync16(buf + (ci * ROWS_IN + rr) * 128 + (c4 << 2),
                      x + ((((size_t)(n * 3 + ci)) * 32 + z) << 14) + ((h0 + rr) << 7) + (c4 << 2));
        }
    };

    prefetch_slice(0, 0);
    prefetch_slice(1, 1);
    prefetch_slice(2, 2);
    prefetch_slice(3, 3);
    asm volatile("cp.async.commit_group;" ::: "memory");
    asm volatile("cp.async.wait_group 0;" ::: "memory");
    __syncthreads();

    const float INF = __int_as_float(0x7f800000);
    float mlo[6][2], mhi[6][2];
    #pragma unroll
    for (int c = 0; c < 6; ++c) {
        mlo[c][0] = INF; mlo[c][1] = INF;
        mhi[c][0] = INF; mhi[c][1] = INF;
    }

    const int    toff = r_loc * 128 + w0;
    const float* wg   = s_w + g * 12;

    int s0 = 0;
    #pragma unroll 1
    for (int c = 0; c < 15; ++c) {
        const int zp = 2 * c + 4;
        if (zp < 32) {
            int sl4 = s0 + 4; if (sl4 >= RING) sl4 -= RING;
            int sl5 = s0 + 5; if (sl5 >= RING) sl5 -= RING;
            prefetch_slice(zp,     sl4);
            prefetch_slice(zp + 1, sl5);
        }
        asm volatile("cp.async.commit_group;" ::: "memory");

        const float* bp[4];
        #pragma unroll
        for (int jj = 0; jj < 4; ++jj) {
            int s = s0 + jj; if (s >= RING) s -= RING;
            bp[jj] = s_sl + s * SLICE_FLOATS + toff;
        }

        u64 acc[2][6][2];
        #pragma unroll
        for (int dz = 0; dz < 2; ++dz)
            #pragma unroll
            for (int cc = 0; cc < 6; ++cc) { acc[dz][cc][0] = 0ull; acc[dz][cc][1] = 0ull; }

        #pragma unroll 1
        for (int ci = 0; ci < 3; ++ci) {
            #pragma unroll
            for (int kh = 0; kh < 3; ++kh) {
                const int ro = (ci * ROWS_IN + kh) * 128;
                // cache this row from all 4 slices
                u64 A0[4], A1[4], A2[4];
                #pragma unroll
                for (int s = 0; s < 4; ++s) {
                    const float* rp = bp[s] + ro;
                    const ulonglong2 t = *reinterpret_cast<const ulonglong2*>(rp);
                    A0[s] = t.x; A1[s] = t.y;
                    A2[s] = *reinterpret_cast<const u64*>(rp + 4);
                }
                const float* wrow0 = wg + ((ci * 3 + kh) * 144);   // kd=0 base (kw-major *48)
                #pragma unroll
                for (int kd = 0; kd < 3; ++kd) {
                    const float* wr = wrow0 + kd * 1296;           // kd stride: 27 taps * 48
                    const u64 p0 = mkpair(A0[kd],     A1[kd]);     // (x1,x2) dz0
                    const u64 p1 = mkpair(A1[kd],     A2[kd]);     // (x3,x4) dz0
                    const u64 q0 = mkpair(A0[kd + 1], A1[kd + 1]); // dz1
                    const u64 q1 = mkpair(A1[kd + 1], A2[kd + 1]);
                    #pragma unroll
                    for (int cp = 0; cp < 3; ++cp) {
                        const ulonglong2 W0 = *reinterpret_cast<const ulonglong2*>(wr + 4 * cp);
                        const ulonglong2 W1 = *reinterpret_cast<const ulonglong2*>(wr + 48 + 4 * cp);
                        const ulonglong2 W2 = *reinterpret_cast<const ulonglong2*>(wr + 96 + 4 * cp);
                        const int c0 = 2 * cp, c1 = 2 * cp + 1;
                        // dz=0 (slice kd)
                        acc[0][c0][0] = ffma2(A0[kd], W0.x, acc[0][c0][0]);
                        acc[0][c0][1] = ffma2(A1[kd], W0.x, acc[0][c0][1]);
                        acc[0][c1][0] = ffma2(A0[kd], W0.y, acc[0][c1][0]);
                        acc[0][c1][1] = ffma2(A1[kd], W0.y, acc[0][c1][1]);
                        acc[0][c0][0] = ffma2(p0, W1.x, acc[0][c0][0]);
                        acc[0][c0][1] = ffma2(p1, W1.x, acc[0][c0][1]);
                        acc[0][c1][0] = ffma2(p0, W1.y, acc[0][c1][0]);
                        acc[0][c1][1] = ffma2(p1, W1.y, acc[0][c1][1]);
                        acc[0][c0][0] = ffma2(A1[kd], W2.x, acc[0][c0][0]);
                        acc[0][c0][1] = ffma2(A2[kd], W2.x, acc[0][c0][1]);
                        acc[0][c1][0] = ffma2(A1[kd], W2.y, acc[0][c1][0]);
                        acc[0][c1][1] = ffma2(A2[kd], W2.y, acc[0][c1][1]);
                        // dz=1 (slice kd+1)
                        acc[1][c0][0] = ffma2(A0[kd+1], W0.x, acc[1][c0][0]);
                        acc[1][c0][1] = ffma2(A1[kd+1], W0.x, acc[1][c0][1]);
                        acc[1][c1][0] = ffma2(A0[kd+1], W0.y, acc[1][c1][0]);
                        acc[1][c1][1] = ffma2(A1[kd+1], W0.y, acc[1][c1][1]);
                        acc[1][c0][0] = ffma2(q0, W1.x, acc[1][c0][0]);
                        acc[1][c0][1] = ffma2(q1, W1.x, acc[1][c0][1]);
                        acc[1][c1][0] = ffma2(q0, W1.y, acc[1][c1][0]);
                        acc[1][c1][1] = ffma2(q1, W1.y, acc[1][c1][1]);
                        acc[1][c0][0] = ffma2(A1[kd+1], W2.x, acc[1][c0][0]);
                        acc[1][c0][1] = ffma2(A2[kd+1], W2.x, acc[1][c0][1]);
                        acc[1][c1][0] = ffma2(A1[kd+1], W2.y, acc[1][c1][0]);
                        acc[1][c1][1] = ffma2(A2[kd+1], W2.y, acc[1][c1][1]);
                    }
                }
            }
        }

        #pragma unroll
        for (int dz = 0; dz < 2; ++dz)
            #pragma unroll
            for (int cc = 0; cc < 6; ++cc)
                #pragma unroll
                for (int p = 0; p < 2; ++p) {
                    mlo[cc][p] = fminf(mlo[cc][p], f2lo(acc[dz][cc][p]));
                    mhi[cc][p] = fminf(mhi[cc][p], f2hi(acc[dz][cc][p]));
                }

        asm volatile("cp.async.wait_group 0;" ::: "memory");
        __syncthreads();

        s0 += 2; if (s0 >= RING) s0 -= RING;
    }

    // ---- min + bias -> smem transpose buffer sf[24][SF_STRIDE] ----
    __syncthreads();                  // all slice/weight reads done; safe to alias
    float* sf = smem;
    {
        const int p0 = r_loc * 126 + w0;
        #pragma unroll
        for (int cc = 0; cc < 6; ++cc) {
            const int co = g * 6 + cc;
            const float bv = __ldg(&bias[co]);
            float* row = sf + co * SF_STRIDE + p0;
            *reinterpret_cast<float2*>(row) = make_float2(mlo[cc][0] + bv, mhi[cc][0] + bv);
            if (w0 + 2 < 126)
                *reinterpret_cast<float2*>(row + 2) = make_float2(mlo[cc][1] + bv, mhi[cc][1] + bv);
        }
    }
    __syncthreads();

    // ---- softmax over 24 channels, write out ----
    if (tid < 252) {
        const int px = tid;           // p = r*126 + w, r in 0..1
        float v[24];
        float m = -INF;
        #pragma unroll
        for (int cc = 0; cc < 24; ++cc) { v[cc] = sf[cc * SF_STRIDE + px]; m = fmaxf(m, v[cc]); }
        float s = 0.f;
        #pragma unroll
        for (int cc = 0; cc < 24; ++cc) { v[cc] = __expf(v[cc] - m); s += v[cc]; }
        const float inv = 1.0f / s;
        float* op = out + (size_t)n * 24 * 15876 + (size_t)h0 * 126 + px;
        #pragma unroll
        for (int cc = 0; cc < 24; ++cc)
            op[(size_t)cc * 15876] = v[cc] * inv;
    }
}

extern "C" void kernel_launch(void* const* d_in, const int* in_sizes, int n_in,
                              void* d_out, int out_size) {
    const float* x    = (const float*)d_in[0];
    const float* wgt  = (const float*)d_in[1];
    const float* bias = (const float*)d_in[2];
    float* out        = (float*)d_out;

    cudaFuncSetAttribute(fused_conv_min_softmax,
                         cudaFuncAttributeMaxDynamicSharedMemorySize, SMEM_BYTES);

    dim3 grid(63, 16);                 // 126/TH h-tiles, 16 batches
    fused_conv_min_softmax<<<grid, 256, SMEM_BYTES>>>(x, wgt, bias, out);
}